// round 1
// baseline (speedup 1.0000x reference)
#include <cuda_runtime.h>
#include <math.h>

#define NNODES 100000
#define NEDGES 1600000
#define FIN 256
#define HID 128
#define COUT 64

// ---------------- scratch (static __device__, no allocation) ----------------
__device__ float g_buf0[NNODES * HID];   // GEMM output (pre-aggregation)
__device__ float g_buf1[NNODES * HID];   // aggregated h (layer output)
__device__ float g_dinv[NNODES];
__device__ int   g_cnt[NNODES];
__device__ int   g_cursor[NNODES];
__device__ int   g_rowptr[NNODES + 1];
__device__ int   g_col[NEDGES];
__device__ float g_w[NEDGES];
__device__ float g_G[HID * HID];
__device__ float g_csum[HID];

// ---------------- preprocessing ----------------
__global__ void k_zero_init() {
    int i = blockIdx.x * blockDim.x + threadIdx.x;
    if (i < NNODES) { g_cnt[i] = 0; g_cursor[i] = 0; }
}

__global__ void k_zero_G() {
    int i = blockIdx.x * blockDim.x + threadIdx.x;
    if (i < HID * HID) g_G[i] = 0.f;
    if (i < HID) g_csum[i] = 0.f;
}

__global__ void k_count(const int* __restrict__ ei) {
    int e = blockIdx.x * blockDim.x + threadIdx.x;
    if (e < NEDGES) atomicAdd(&g_cnt[ei[e]], 1);
}

__global__ void k_dinv() {
    int i = blockIdx.x * blockDim.x + threadIdx.x;
    if (i < NNODES) g_dinv[i] = rsqrtf((float)(g_cnt[i] + 1));  // +1 self loop
}

// single-block exclusive scan of g_cnt -> g_rowptr
__global__ void k_scan() {
    __shared__ int part[1024];
    int tid = threadIdx.x;
    const int chunk = (NNODES + 1023) / 1024;
    int st = tid * chunk;
    int en = st + chunk; if (en > NNODES) en = NNODES;
    int s = 0;
    for (int i = st; i < en; i++) s += g_cnt[i];
    part[tid] = s;
    __syncthreads();
    // Hillis-Steele inclusive scan
    for (int off = 1; off < 1024; off <<= 1) {
        int v = (tid >= off) ? part[tid - off] : 0;
        __syncthreads();
        part[tid] += v;
        __syncthreads();
    }
    int run = (tid == 0) ? 0 : part[tid - 1];
    for (int i = st; i < en; i++) { g_rowptr[i] = run; run += g_cnt[i]; }
    if (tid == 1023) g_rowptr[NNODES] = part[1023];
}

__global__ void k_fill(const int* __restrict__ ei) {
    int e = blockIdx.x * blockDim.x + threadIdx.x;
    if (e >= NEDGES) return;
    int r = ei[e];
    int c = ei[NEDGES + e];
    int pos = g_rowptr[r] + atomicAdd(&g_cursor[r], 1);
    g_col[pos] = c;
    g_w[pos] = g_dinv[r] * g_dinv[c];
}

// ---------------- dense GEMM: C[N,D] = act(A[N,K]) @ W[K,D] ----------------
// BM=64 rows per block, 256 threads: tx in [0,32) col-group, ty in [0,8) row-group.
template <int K, int D, bool RELU>
__global__ void k_gemm(const float* __restrict__ A, const float* __restrict__ W,
                       float* __restrict__ C) {
    const int BM = 64, BK = 16;
    const int TN = D / 32;           // 4 (D=128) or 2 (D=64)
    __shared__ float As[BK][BM + 1];
    __shared__ float Bs[BK][D];
    int tid = threadIdx.x;
    int tx = tid & 31, ty = tid >> 5;
    int row0 = blockIdx.x * BM;

    float acc[8][TN];
#pragma unroll
    for (int i = 0; i < 8; i++)
#pragma unroll
        for (int j = 0; j < TN; j++) acc[i][j] = 0.f;

    for (int kk = 0; kk < K; kk += BK) {
        // load A tile (BM x BK), coalesced along k within a row
#pragma unroll
        for (int i = 0; i < (BM * BK) / 256; i++) {
            int idx = tid + i * 256;
            int m = idx / BK, k = idx % BK;
            int r = row0 + m;
            float v = (r < NNODES) ? A[r * K + kk + k] : 0.f;
            if (RELU) v = fmaxf(v, 0.f);
            As[k][m] = v;
        }
        // load B tile (BK x D), fully coalesced
#pragma unroll
        for (int i = 0; i < (BK * D) / 256; i++) {
            int idx = tid + i * 256;
            int k = idx / D, n = idx % D;
            Bs[k][n] = W[(kk + k) * D + n];
        }
        __syncthreads();
#pragma unroll
        for (int k = 0; k < BK; k++) {
            float b[TN];
#pragma unroll
            for (int j = 0; j < TN; j++) b[j] = Bs[k][tx * TN + j];
#pragma unroll
            for (int i = 0; i < 8; i++) {
                float a = As[k][ty * 8 + i];
#pragma unroll
                for (int j = 0; j < TN; j++) acc[i][j] = fmaf(a, b[j], acc[i][j]);
            }
        }
        __syncthreads();
    }
#pragma unroll
    for (int i = 0; i < 8; i++) {
        int r = row0 + ty * 8 + i;
        if (r < NNODES) {
#pragma unroll
            for (int j = 0; j < TN; j++) C[r * D + tx * TN + j] = acc[i][j];
        }
    }
}

// ---------------- sparse aggregation: out[i] = dinv[i]^2*t[i] + sum_e w*t[col] ---
__global__ void k_agg128(const float* __restrict__ tmp, float* __restrict__ out) {
    int gw = (blockIdx.x * blockDim.x + threadIdx.x) >> 5;
    int lane = threadIdx.x & 31;
    if (gw >= NNODES) return;
    const float4* t4 = (const float4*)tmp;
    float di = g_dinv[gw];
    float s = di * di;
    float4 v = t4[gw * 32 + lane];
    float4 acc = make_float4(v.x * s, v.y * s, v.z * s, v.w * s);
    int e = g_rowptr[gw], en = g_rowptr[gw + 1];
    for (; e < en; e++) {
        int c = g_col[e];
        float ww = g_w[e];
        float4 u = t4[c * 32 + lane];
        acc.x = fmaf(ww, u.x, acc.x);
        acc.y = fmaf(ww, u.y, acc.y);
        acc.z = fmaf(ww, u.z, acc.z);
        acc.w = fmaf(ww, u.w, acc.w);
    }
    ((float4*)out)[gw * 32 + lane] = acc;
}

__global__ void k_agg64(const float* __restrict__ tmp, float* __restrict__ out) {
    int gw = (blockIdx.x * blockDim.x + threadIdx.x) >> 5;
    int lane = threadIdx.x & 31;
    if (gw >= NNODES) return;
    const float2* t2 = (const float2*)tmp;
    float di = g_dinv[gw];
    float s = di * di;
    float2 v = t2[gw * 32 + lane];
    float2 acc = make_float2(v.x * s, v.y * s);
    int e = g_rowptr[gw], en = g_rowptr[gw + 1];
    for (; e < en; e++) {
        int c = g_col[e];
        float ww = g_w[e];
        float2 u = t2[c * 32 + lane];
        acc.x = fmaf(ww, u.x, acc.x);
        acc.y = fmaf(ww, u.y, acc.y);
    }
    ((float2*)out)[gw * 32 + lane] = acc;
}

// ---------------- Gram matrix G = h^T h + column sums ----------------
template <int D>
__global__ void k_gram(const float* __restrict__ h) {
    const int RB = 8;
    const int TT = D / 16;           // 8 (D=128) or 4 (D=64)
    __shared__ float srow[RB][D];
    int tid = threadIdx.x;
    int tx = tid & 15, ty = tid >> 4;

    float acc[TT][TT];
    float cs[TT];
#pragma unroll
    for (int i = 0; i < TT; i++) {
        cs[i] = 0.f;
#pragma unroll
        for (int j = 0; j < TT; j++) acc[i][j] = 0.f;
    }

    for (int r0 = blockIdx.x * RB; r0 < NNODES; r0 += gridDim.x * RB) {
        int nr = NNODES - r0; if (nr > RB) nr = RB;
        for (int idx = tid; idx < nr * D; idx += 256)
            srow[idx / D][idx % D] = h[(r0 + idx / D) * D + idx % D];
        __syncthreads();
        for (int rr = 0; rr < nr; rr++) {
            float a[TT], b[TT];
#pragma unroll
            for (int i = 0; i < TT; i++) {
                a[i] = srow[rr][ty * TT + i];
                b[i] = srow[rr][tx * TT + i];
            }
#pragma unroll
            for (int i = 0; i < TT; i++)
#pragma unroll
                for (int j = 0; j < TT; j++) acc[i][j] = fmaf(a[i], b[j], acc[i][j]);
            if (ty == 0)
#pragma unroll
                for (int j = 0; j < TT; j++) cs[j] += b[j];
        }
        __syncthreads();
    }
#pragma unroll
    for (int i = 0; i < TT; i++)
#pragma unroll
        for (int j = 0; j < TT; j++)
            atomicAdd(&g_G[(ty * TT + i) * D + tx * TT + j], acc[i][j]);
    if (ty == 0)
#pragma unroll
        for (int j = 0; j < TT; j++) atomicAdd(&g_csum[tx * TT + j], cs[j]);
}

// ---------------- correlation metric finalize (single block) ----------------
template <int D>
__global__ void k_finalize(float* __restrict__ dst) {
    __shared__ float sd[D];
    __shared__ float red[256];
    int tid = threadIdx.x;
    const float invN = 1.0f / (float)NNODES;
    if (tid < D) {
        float cjj = g_G[tid * D + tid] - g_csum[tid] * g_csum[tid] * invN;
        sd[tid] = sqrtf(fmaxf(cjj, 1e-12f));
    }
    __syncthreads();
    float sum = 0.f;
    for (int idx = tid; idx < D * D; idx += 256) {
        int j = idx / D, k = idx % D;
        if (k > j) {
            float cov = g_G[idx] - g_csum[j] * g_csum[k] * invN;
            sum += fabsf(cov / (sd[j] * sd[k]));
        }
    }
    red[tid] = sum;
    __syncthreads();
    for (int off = 128; off > 0; off >>= 1) {
        if (tid < off) red[tid] += red[tid + off];
        __syncthreads();
    }
    if (tid == 0) *dst = red[0] / (float)(D * (D - 1) / 2);
}

// ---------------- launch ----------------
extern "C" void kernel_launch(void* const* d_in, const int* in_sizes, int n_in,
                              void* d_out, int out_size) {
    const float* x  = (const float*)d_in[0];
    const int*   ei = (const int*)d_in[1];
    const float* W0 = (const float*)d_in[2];
    const float* W1 = (const float*)d_in[3];
    const float* W2 = (const float*)d_in[4];
    const float* W3 = (const float*)d_in[5];
    float* out = (float*)d_out;

    float *buf0, *buf1;
    cudaGetSymbolAddress((void**)&buf0, g_buf0);
    cudaGetSymbolAddress((void**)&buf1, g_buf1);

    const int TB = 256;
    const int nbN = (NNODES + TB - 1) / TB;
    const int nbE = (NEDGES + TB - 1) / TB;
    const int nbG = (NNODES + 63) / 64;          // GEMM blocks (BM=64)
    const int nbA = (NNODES + 7) / 8;            // agg blocks (8 warps/block)

    // preprocessing: degrees, dinv, CSR
    k_zero_init<<<nbN, TB>>>();
    k_count<<<nbE, TB>>>(ei);
    k_dinv<<<nbN, TB>>>();
    k_scan<<<1, 1024>>>();
    k_fill<<<nbE, TB>>>(ei);

    // layer 0: x[N,256] @ W0 -> agg
    k_gemm<FIN, HID, false><<<nbG, TB>>>(x, W0, buf0);
    k_agg128<<<nbA, TB>>>(buf0, buf1);
    // layer 1: relu(h0) @ W1 -> agg
    k_gemm<HID, HID, true><<<nbG, TB>>>(buf1, W1, buf0);
    k_agg128<<<nbA, TB>>>(buf0, buf1);
    // layer 2: relu(h1) @ W2 -> agg (corr_2 on pre-relu h2)
    k_gemm<HID, HID, true><<<nbG, TB>>>(buf1, W2, buf0);
    k_agg128<<<nbA, TB>>>(buf0, buf1);

    // corr_2 metric on h2
    k_zero_G<<<(HID * HID + TB - 1) / TB, TB>>>();
    k_gram<HID><<<296, TB>>>(buf1);
    k_finalize<HID><<<1, TB>>>(out + NNODES * COUT);

    // layer 3: relu(h2) @ W3 -> agg directly into d_out
    k_gemm<HID, COUT, true><<<nbG, TB>>>(buf1, W3, buf0);
    k_agg64<<<nbA, TB>>>(buf0, out);

    // corr metric on h3
    k_zero_G<<<(HID * HID + TB - 1) / TB, TB>>>();
    k_gram<COUT><<<296, TB>>>(out);
    k_finalize<COUT><<<1, TB>>>(out + NNODES * COUT + 1);
}

// round 2
// speedup vs baseline: 1.1007x; 1.1007x over previous
#include <cuda_runtime.h>
#include <math.h>

#define NNODES 100000
#define NEDGES 1600000
#define FIN 256
#define HID 128
#define COUT 64

#define SCAN_TPB 256
#define SCAN_ELEMS 8
#define SCAN_CHUNK (SCAN_TPB * SCAN_ELEMS)                 // 2048
#define SCAN_NB ((NNODES + SCAN_CHUNK - 1) / SCAN_CHUNK)   // 49

// ---------------- scratch (static __device__, no allocation) ----------------
__device__ float g_buf0[NNODES * HID];   // GEMM output (pre-aggregation)
__device__ float g_buf1[NNODES * HID];   // aggregated h (layer output)
__device__ float g_dinv[NNODES];
__device__ int   g_cnt[NNODES];
__device__ int   g_cursor[NNODES];
__device__ int   g_rowptr[NNODES + 1];
__device__ int   g_col[NEDGES];
__device__ float g_w[NEDGES];
__device__ float g_G[HID * HID];
__device__ float g_csum[HID];
__device__ int   g_bsum[SCAN_NB];

// ---------------- preprocessing ----------------
__global__ void k_zero_init() {
    int i = blockIdx.x * blockDim.x + threadIdx.x;
    if (i < NNODES) { g_cnt[i] = 0; g_cursor[i] = 0; }
}

__global__ void k_zero_G() {
    int i = blockIdx.x * blockDim.x + threadIdx.x;
    if (i < HID * HID) g_G[i] = 0.f;
    if (i < HID) g_csum[i] = 0.f;
}

__global__ void k_count(const int* __restrict__ ei) {
    int e = blockIdx.x * blockDim.x + threadIdx.x;
    if (e < NEDGES) atomicAdd(&g_cnt[ei[e]], 1);
}

__global__ void k_dinv() {
    int i = blockIdx.x * blockDim.x + threadIdx.x;
    if (i < NNODES) g_dinv[i] = rsqrtf((float)(g_cnt[i] + 1));  // +1 self loop
}

// ---- multi-block exclusive scan of g_cnt -> g_rowptr ----
// pass 1: per-block totals
__global__ void k_scan1() {
    __shared__ int warp_s[SCAN_TPB / 32];
    int tid = threadIdx.x, blk = blockIdx.x;
    int base = blk * SCAN_CHUNK + tid * SCAN_ELEMS;
    int s = 0;
#pragma unroll
    for (int i = 0; i < SCAN_ELEMS; i++) {
        int idx = base + i;
        if (idx < NNODES) s += g_cnt[idx];
    }
    for (int o = 16; o > 0; o >>= 1) s += __shfl_down_sync(0xffffffffu, s, o);
    if ((tid & 31) == 0) warp_s[tid >> 5] = s;
    __syncthreads();
    if (tid < SCAN_TPB / 32) {
        int w = warp_s[tid];
        for (int o = (SCAN_TPB / 64); o > 0; o >>= 1)
            w += __shfl_down_sync(0xffu, w, o);
        if (tid == 0) g_bsum[blk] = w;
    }
}

// pass 2: exclusive scan of the SCAN_NB block totals (one small block)
__global__ void k_scan2() {
    __shared__ int sh[64];
    int tid = threadIdx.x;
    sh[tid] = (tid < SCAN_NB) ? g_bsum[tid] : 0;
    __syncthreads();
    for (int o = 1; o < 64; o <<= 1) {
        int v = (tid >= o) ? sh[tid - o] : 0;
        __syncthreads();
        sh[tid] += v;
        __syncthreads();
    }
    if (tid < SCAN_NB) g_bsum[tid] = (tid == 0) ? 0 : sh[tid - 1];
    if (tid == 0) g_rowptr[NNODES] = sh[SCAN_NB - 1];
}

// pass 3: per-block local scan + global offset -> rowptr
__global__ void k_scan3() {
    __shared__ int tsum[SCAN_TPB];
    int tid = threadIdx.x, blk = blockIdx.x;
    int base = blk * SCAN_CHUNK + tid * SCAN_ELEMS;
    int c[SCAN_ELEMS];
    int s = 0;
#pragma unroll
    for (int i = 0; i < SCAN_ELEMS; i++) {
        int idx = base + i;
        c[i] = (idx < NNODES) ? g_cnt[idx] : 0;
        s += c[i];
    }
    tsum[tid] = s;
    __syncthreads();
    for (int o = 1; o < SCAN_TPB; o <<= 1) {
        int v = (tid >= o) ? tsum[tid - o] : 0;
        __syncthreads();
        tsum[tid] += v;
        __syncthreads();
    }
    int run = g_bsum[blk] + ((tid == 0) ? 0 : tsum[tid - 1]);
#pragma unroll
    for (int i = 0; i < SCAN_ELEMS; i++) {
        int idx = base + i;
        if (idx < NNODES) { g_rowptr[idx] = run; run += c[i]; }
    }
}

__global__ void k_fill(const int* __restrict__ ei) {
    int e = blockIdx.x * blockDim.x + threadIdx.x;
    if (e >= NEDGES) return;
    int r = ei[e];
    int c = ei[NEDGES + e];
    int pos = g_rowptr[r] + atomicAdd(&g_cursor[r], 1);
    g_col[pos] = c;
    g_w[pos] = g_dinv[r] * g_dinv[c];
}

// ---------------- dense GEMM: C[N,D] = act(A[N,K]) @ W[K,D] ----------------
// BM=128 rows/block, 256 threads as 16x16, each thread computes 8 x (D/16).
template <int K, int D, bool RELU>
__global__ __launch_bounds__(256) void k_gemm(const float* __restrict__ A,
                                              const float* __restrict__ W,
                                              float* __restrict__ C) {
    const int BM = 128, BK = 16;
    const int TN = D / 16;                 // 8 (D=128) or 4 (D=64)
    __shared__ float As[BK][BM + 4];
    __shared__ float Bs[BK][D];
    int tid = threadIdx.x;
    int tx = tid & 15, ty = tid >> 4;
    int row0 = blockIdx.x * BM;

    float acc[8][TN];
#pragma unroll
    for (int i = 0; i < 8; i++)
#pragma unroll
        for (int j = 0; j < TN; j++) acc[i][j] = 0.f;

    for (int kk = 0; kk < K; kk += BK) {
        // A tile: 128x16 = 512 float4s, 2 per thread
#pragma unroll
        for (int i = 0; i < 2; i++) {
            int q = tid + i * 256;
            int m = q >> 2, kq = (q & 3) * 4;
            int r = row0 + m;
            float4 v = make_float4(0.f, 0.f, 0.f, 0.f);
            if (r < NNODES) v = *(const float4*)&A[r * K + kk + kq];
            if (RELU) {
                v.x = fmaxf(v.x, 0.f); v.y = fmaxf(v.y, 0.f);
                v.z = fmaxf(v.z, 0.f); v.w = fmaxf(v.w, 0.f);
            }
            As[kq + 0][m] = v.x; As[kq + 1][m] = v.y;
            As[kq + 2][m] = v.z; As[kq + 3][m] = v.w;
        }
        // B tile: BKxD float4s
#pragma unroll
        for (int i = 0; i < (BK * D) / 4 / 256; i++) {
            int q = tid + i * 256;
            int k = q / (D / 4), n = (q % (D / 4)) * 4;
            *(float4*)&Bs[k][n] = *(const float4*)&W[(kk + k) * D + n];
        }
        __syncthreads();
#pragma unroll
        for (int k = 0; k < BK; k++) {
            float a[8], b[TN];
            *(float4*)&a[0] = *(float4*)&As[k][ty * 8];
            *(float4*)&a[4] = *(float4*)&As[k][ty * 8 + 4];
#pragma unroll
            for (int j = 0; j < TN; j += 4)
                *(float4*)&b[j] = *(float4*)&Bs[k][tx * TN + j];
#pragma unroll
            for (int i = 0; i < 8; i++)
#pragma unroll
                for (int j = 0; j < TN; j++)
                    acc[i][j] = fmaf(a[i], b[j], acc[i][j]);
        }
        __syncthreads();
    }
#pragma unroll
    for (int i = 0; i < 8; i++) {
        int r = row0 + ty * 8 + i;
        if (r < NNODES) {
#pragma unroll
            for (int j = 0; j < TN; j += 4)
                *(float4*)&C[r * D + tx * TN + j] = *(float4*)&acc[i][j];
        }
    }
}

// ---------------- sparse aggregation: out[i] = dinv[i]^2*t[i] + sum_e w*t[col]
__global__ void k_agg128(const float* __restrict__ tmp, float* __restrict__ out) {
    int gw = (blockIdx.x * blockDim.x + threadIdx.x) >> 5;
    int lane = threadIdx.x & 31;
    if (gw >= NNODES) return;
    const float4* __restrict__ t4 = (const float4*)tmp;
    float di = g_dinv[gw];
    float s = di * di;
    float4 v = t4[gw * 32 + lane];
    float4 acc = make_float4(v.x * s, v.y * s, v.z * s, v.w * s);
    float4 acc2 = make_float4(0.f, 0.f, 0.f, 0.f);
    int e = g_rowptr[gw], en = g_rowptr[gw + 1];
    for (; e + 1 < en; e += 2) {
        int c0 = g_col[e], c1 = g_col[e + 1];
        float w0 = g_w[e], w1 = g_w[e + 1];
        float4 u0 = t4[c0 * 32 + lane];
        float4 u1 = t4[c1 * 32 + lane];
        acc.x = fmaf(w0, u0.x, acc.x);   acc.y = fmaf(w0, u0.y, acc.y);
        acc.z = fmaf(w0, u0.z, acc.z);   acc.w = fmaf(w0, u0.w, acc.w);
        acc2.x = fmaf(w1, u1.x, acc2.x); acc2.y = fmaf(w1, u1.y, acc2.y);
        acc2.z = fmaf(w1, u1.z, acc2.z); acc2.w = fmaf(w1, u1.w, acc2.w);
    }
    if (e < en) {
        int c0 = g_col[e];
        float w0 = g_w[e];
        float4 u0 = t4[c0 * 32 + lane];
        acc.x = fmaf(w0, u0.x, acc.x); acc.y = fmaf(w0, u0.y, acc.y);
        acc.z = fmaf(w0, u0.z, acc.z); acc.w = fmaf(w0, u0.w, acc.w);
    }
    acc.x += acc2.x; acc.y += acc2.y; acc.z += acc2.z; acc.w += acc2.w;
    ((float4*)out)[gw * 32 + lane] = acc;
}

__global__ void k_agg64(const float* __restrict__ tmp, float* __restrict__ out) {
    int gw = (blockIdx.x * blockDim.x + threadIdx.x) >> 5;
    int lane = threadIdx.x & 31;
    if (gw >= NNODES) return;
    const float2* __restrict__ t2 = (const float2*)tmp;
    float di = g_dinv[gw];
    float s = di * di;
    float2 v = t2[gw * 32 + lane];
    float2 acc = make_float2(v.x * s, v.y * s);
    float2 acc2 = make_float2(0.f, 0.f);
    int e = g_rowptr[gw], en = g_rowptr[gw + 1];
    for (; e + 1 < en; e += 2) {
        int c0 = g_col[e], c1 = g_col[e + 1];
        float w0 = g_w[e], w1 = g_w[e + 1];
        float2 u0 = t2[c0 * 32 + lane];
        float2 u1 = t2[c1 * 32 + lane];
        acc.x = fmaf(w0, u0.x, acc.x);   acc.y = fmaf(w0, u0.y, acc.y);
        acc2.x = fmaf(w1, u1.x, acc2.x); acc2.y = fmaf(w1, u1.y, acc2.y);
    }
    if (e < en) {
        int c0 = g_col[e];
        float w0 = g_w[e];
        float2 u0 = t2[c0 * 32 + lane];
        acc.x = fmaf(w0, u0.x, acc.x); acc.y = fmaf(w0, u0.y, acc.y);
    }
    acc.x += acc2.x; acc.y += acc2.y;
    ((float2*)out)[gw * 32 + lane] = acc;
}

// ---------------- Gram matrix G = h^T h + column sums ----------------
template <int D>
__global__ void k_gram(const float* __restrict__ h) {
    const int RB = 8;
    const int TT = D / 16;           // 8 (D=128) or 4 (D=64)
    __shared__ float srow[RB][D];
    int tid = threadIdx.x;
    int tx = tid & 15, ty = tid >> 4;

    float acc[TT][TT];
    float cs[TT];
#pragma unroll
    for (int i = 0; i < TT; i++) {
        cs[i] = 0.f;
#pragma unroll
        for (int j = 0; j < TT; j++) acc[i][j] = 0.f;
    }

    for (int r0 = blockIdx.x * RB; r0 < NNODES; r0 += gridDim.x * RB) {
        int nr = NNODES - r0; if (nr > RB) nr = RB;
        for (int idx = tid; idx < nr * D; idx += 256)
            srow[idx / D][idx % D] = h[(r0 + idx / D) * D + idx % D];
        __syncthreads();
        for (int rr = 0; rr < nr; rr++) {
            float a[TT], b[TT];
#pragma unroll
            for (int i = 0; i < TT; i++) {
                a[i] = srow[rr][ty * TT + i];
                b[i] = srow[rr][tx * TT + i];
            }
#pragma unroll
            for (int i = 0; i < TT; i++)
#pragma unroll
                for (int j = 0; j < TT; j++) acc[i][j] = fmaf(a[i], b[j], acc[i][j]);
            if (ty == 0)
#pragma unroll
                for (int j = 0; j < TT; j++) cs[j] += b[j];
        }
        __syncthreads();
    }
#pragma unroll
    for (int i = 0; i < TT; i++)
#pragma unroll
        for (int j = 0; j < TT; j++)
            atomicAdd(&g_G[(ty * TT + i) * D + tx * TT + j], acc[i][j]);
    if (ty == 0)
#pragma unroll
        for (int j = 0; j < TT; j++) atomicAdd(&g_csum[tx * TT + j], cs[j]);
}

// ---------------- correlation metric finalize (single block) ----------------
template <int D>
__global__ void k_finalize(float* __restrict__ dst) {
    __shared__ float sd[D];
    __shared__ float red[256];
    int tid = threadIdx.x;
    const float invN = 1.0f / (float)NNODES;
    if (tid < D) {
        float cjj = g_G[tid * D + tid] - g_csum[tid] * g_csum[tid] * invN;
        sd[tid] = sqrtf(fmaxf(cjj, 1e-12f));
    }
    __syncthreads();
    float sum = 0.f;
    for (int idx = tid; idx < D * D; idx += 256) {
        int j = idx / D, k = idx % D;
        if (k > j) {
            float cov = g_G[idx] - g_csum[j] * g_csum[k] * invN;
            sum += fabsf(cov / (sd[j] * sd[k]));
        }
    }
    red[tid] = sum;
    __syncthreads();
    for (int off = 128; off > 0; off >>= 1) {
        if (tid < off) red[tid] += red[tid + off];
        __syncthreads();
    }
    if (tid == 0) *dst = red[0] / (float)(D * (D - 1) / 2);
}

// ---------------- launch ----------------
extern "C" void kernel_launch(void* const* d_in, const int* in_sizes, int n_in,
                              void* d_out, int out_size) {
    const float* x  = (const float*)d_in[0];
    const int*   ei = (const int*)d_in[1];
    const float* W0 = (const float*)d_in[2];
    const float* W1 = (const float*)d_in[3];
    const float* W2 = (const float*)d_in[4];
    const float* W3 = (const float*)d_in[5];
    float* out = (float*)d_out;

    float *buf0, *buf1;
    cudaGetSymbolAddress((void**)&buf0, g_buf0);
    cudaGetSymbolAddress((void**)&buf1, g_buf1);

    const int TB = 256;
    const int nbN = (NNODES + TB - 1) / TB;
    const int nbE = (NEDGES + TB - 1) / TB;
    const int nbG = (NNODES + 127) / 128;        // GEMM blocks (BM=128)
    const int nbA = (NNODES + 7) / 8;            // agg blocks (8 warps/block)

    // preprocessing: degrees, dinv, CSR
    k_zero_init<<<nbN, TB>>>();
    k_count<<<nbE, TB>>>(ei);
    k_dinv<<<nbN, TB>>>();
    k_scan1<<<SCAN_NB, SCAN_TPB>>>();
    k_scan2<<<1, 64>>>();
    k_scan3<<<SCAN_NB, SCAN_TPB>>>();
    k_fill<<<nbE, TB>>>(ei);

    // layer 0: x[N,256] @ W0 -> agg
    k_gemm<FIN, HID, false><<<nbG, TB>>>(x, W0, buf0);
    k_agg128<<<nbA, TB>>>(buf0, buf1);
    // layer 1: relu(h0) @ W1 -> agg
    k_gemm<HID, HID, true><<<nbG, TB>>>(buf1, W1, buf0);
    k_agg128<<<nbA, TB>>>(buf0, buf1);
    // layer 2: relu(h1) @ W2 -> agg (corr_2 on pre-relu h2)
    k_gemm<HID, HID, true><<<nbG, TB>>>(buf1, W2, buf0);
    k_agg128<<<nbA, TB>>>(buf0, buf1);

    // corr_2 metric on h2
    k_zero_G<<<(HID * HID + TB - 1) / TB, TB>>>();
    k_gram<HID><<<296, TB>>>(buf1);
    k_finalize<HID><<<1, TB>>>(out + NNODES * COUT);

    // layer 3: relu(h2) @ W3 -> agg directly into d_out
    k_gemm<HID, COUT, true><<<nbG, TB>>>(buf1, W3, buf0);
    k_agg64<<<nbA, TB>>>(buf0, out);

    // corr metric on h3
    k_zero_G<<<(HID * HID + TB - 1) / TB, TB>>>();
    k_gram<COUT><<<296, TB>>>(out);
    k_finalize<COUT><<<1, TB>>>(out + NNODES * COUT + 1);
}

// round 4
// speedup vs baseline: 1.3376x; 1.2152x over previous
#include <cuda_runtime.h>
#include <cuda_bf16.h>
#include <math.h>
#include <stdint.h>

#define NNODES 100000
#define NEDGES 1600000
#define FIN 256
#define HID 128
#define COUT 64

#define SCAN_TPB 256
#define SCAN_ELEMS 8
#define SCAN_CHUNK (SCAN_TPB * SCAN_ELEMS)                 // 2048
#define SCAN_NB ((NNODES + SCAN_CHUNK - 1) / SCAN_CHUNK)   // 49

// ---------------- scratch (static __device__, no allocation) ----------------
__device__ float g_buf0[NNODES * HID];   // GEMM output (pre-aggregation)
__device__ float g_buf1[NNODES * HID];   // aggregated h (layer output)
__device__ float g_dinv[NNODES];
__device__ int   g_cnt[NNODES];
__device__ int   g_cursor[NNODES];
__device__ int   g_rowptr[NNODES + 1];
__device__ int   g_col[NEDGES];
__device__ float g_w[NEDGES];
__device__ float g_G[HID * HID];
__device__ float g_csum[HID];
__device__ int   g_bsum[SCAN_NB];

// split-bf16 transposed weights: Wt[d][k] = W[k][d]
__device__ __nv_bfloat16 g_w0h[HID * FIN],  g_w0l[HID * FIN];
__device__ __nv_bfloat16 g_w1h[HID * HID],  g_w1l[HID * HID];
__device__ __nv_bfloat16 g_w2h[HID * HID],  g_w2l[HID * HID];
__device__ __nv_bfloat16 g_w3h[COUT * HID], g_w3l[COUT * HID];

// ---------------- helpers ----------------
__device__ __forceinline__ uint32_t smem_u32(const void* p) {
    uint32_t a;
    asm("{ .reg .u64 t; cvta.to.shared.u64 t, %1; cvt.u32.u64 %0, t; }"
        : "=r"(a) : "l"(p));
    return a;
}
__device__ __forceinline__ uint32_t sw128(uint32_t off) {
    return off ^ ((off >> 3) & 0x70);
}
__device__ __forceinline__ void ldsm4(uint32_t* r, uint32_t addr) {
    asm volatile("ldmatrix.sync.aligned.m8n8.x4.shared.b16 {%0,%1,%2,%3}, [%4];"
                 : "=r"(r[0]), "=r"(r[1]), "=r"(r[2]), "=r"(r[3]) : "r"(addr));
}
__device__ __forceinline__ void mma16816(float* c, const uint32_t* a,
                                         const uint32_t* b) {
    asm volatile(
        "mma.sync.aligned.m16n8k16.row.col.f32.bf16.bf16.f32 "
        "{%0,%1,%2,%3}, {%4,%5,%6,%7}, {%8,%9}, {%0,%1,%2,%3};"
        : "+f"(c[0]), "+f"(c[1]), "+f"(c[2]), "+f"(c[3])
        : "r"(a[0]), "r"(a[1]), "r"(a[2]), "r"(a[3]), "r"(b[0]), "r"(b[1]));
}

// ---------------- preprocessing ----------------
__global__ void k_zero_init() {
    int i = blockIdx.x * blockDim.x + threadIdx.x;
    if (i < NNODES) { g_cnt[i] = 0; g_cursor[i] = 0; }
}

__global__ void k_zero_G() {
    int i = blockIdx.x * blockDim.x + threadIdx.x;
    if (i < HID * HID) g_G[i] = 0.f;
    if (i < HID) g_csum[i] = 0.f;
}

__global__ void k_count(const int* __restrict__ ei) {
    int e = blockIdx.x * blockDim.x + threadIdx.x;
    if (e < NEDGES) atomicAdd(&g_cnt[ei[e]], 1);
}

__global__ void k_dinv() {
    int i = blockIdx.x * blockDim.x + threadIdx.x;
    if (i < NNODES) g_dinv[i] = rsqrtf((float)(g_cnt[i] + 1));  // +1 self loop
}

__global__ void k_scan1() {
    __shared__ int warp_s[SCAN_TPB / 32];
    int tid = threadIdx.x, blk = blockIdx.x;
    int base = blk * SCAN_CHUNK + tid * SCAN_ELEMS;
    int s = 0;
#pragma unroll
    for (int i = 0; i < SCAN_ELEMS; i++) {
        int idx = base + i;
        if (idx < NNODES) s += g_cnt[idx];
    }
    for (int o = 16; o > 0; o >>= 1) s += __shfl_down_sync(0xffffffffu, s, o);
    if ((tid & 31) == 0) warp_s[tid >> 5] = s;
    __syncthreads();
    if (tid < SCAN_TPB / 32) {
        int w = warp_s[tid];
        for (int o = (SCAN_TPB / 64); o > 0; o >>= 1)
            w += __shfl_down_sync(0xffu, w, o);
        if (tid == 0) g_bsum[blk] = w;
    }
}

__global__ void k_scan2() {
    __shared__ int sh[64];
    int tid = threadIdx.x;
    sh[tid] = (tid < SCAN_NB) ? g_bsum[tid] : 0;
    __syncthreads();
    for (int o = 1; o < 64; o <<= 1) {
        int v = (tid >= o) ? sh[tid - o] : 0;
        __syncthreads();
        sh[tid] += v;
        __syncthreads();
    }
    if (tid < SCAN_NB) g_bsum[tid] = (tid == 0) ? 0 : sh[tid - 1];
    if (tid == 0) g_rowptr[NNODES] = sh[SCAN_NB - 1];
}

__global__ void k_scan3() {
    __shared__ int tsum[SCAN_TPB];
    int tid = threadIdx.x, blk = blockIdx.x;
    int base = blk * SCAN_CHUNK + tid * SCAN_ELEMS;
    int c[SCAN_ELEMS];
    int s = 0;
#pragma unroll
    for (int i = 0; i < SCAN_ELEMS; i++) {
        int idx = base + i;
        c[i] = (idx < NNODES) ? g_cnt[idx] : 0;
        s += c[i];
    }
    tsum[tid] = s;
    __syncthreads();
    for (int o = 1; o < SCAN_TPB; o <<= 1) {
        int v = (tid >= o) ? tsum[tid - o] : 0;
        __syncthreads();
        tsum[tid] += v;
        __syncthreads();
    }
    int run = g_bsum[blk] + ((tid == 0) ? 0 : tsum[tid - 1]);
#pragma unroll
    for (int i = 0; i < SCAN_ELEMS; i++) {
        int idx = base + i;
        if (idx < NNODES) { g_rowptr[idx] = run; run += c[i]; }
    }
}

__global__ void k_fill(const int* __restrict__ ei) {
    int e = blockIdx.x * blockDim.x + threadIdx.x;
    if (e >= NEDGES) return;
    int r = ei[e];
    int c = ei[NEDGES + e];
    int pos = g_rowptr[r] + atomicAdd(&g_cursor[r], 1);
    g_col[pos] = c;
    g_w[pos] = g_dinv[r] * g_dinv[c];
}

// ---------------- weight prep: W[K,D] fp32 -> Wt hi/lo bf16 [D][K] ----------
template <int K, int D>
__global__ void k_prepW(const float* __restrict__ W,
                        __nv_bfloat16* __restrict__ Wh,
                        __nv_bfloat16* __restrict__ Wl) {
    int i = blockIdx.x * blockDim.x + threadIdx.x;
    if (i >= K * D) return;
    int n = i / K, k = i % K;
    float v = W[k * D + n];
    __nv_bfloat16 h = __float2bfloat16_rn(v);
    __nv_bfloat16 l = __float2bfloat16_rn(v - __bfloat162float(h));
    Wh[n * K + k] = h;
    Wl[n * K + k] = l;
}

// ---------------- tensor-core split-bf16 GEMM: C = act(A[N,K]) @ W[K,D] ----
// CTA: 128 rows x D cols, 256 threads (8 warps as 4x2). Warp tile 32 x D/2.
// K chunked by 64 into SW128-swizzled smem (128B rows); mma.sync m16n8k16.
template <int K, int D, bool RELU>
__global__ __launch_bounds__(256) void k_tgemm(const float* __restrict__ A,
                                               const __nv_bfloat16* __restrict__ Bh,
                                               const __nv_bfloat16* __restrict__ Bl,
                                               float* __restrict__ C) {
    extern __shared__ __align__(1024) uint8_t smem[];
    const int CK = 64;                   // K elems per chunk
    const int NCH = K / CK;
    const int WN = D / 2;                // 64 or 32
    const int NT = WN / 8;               // 8 or 4 n8-tiles per warp
    const int OFF_AH = 0;
    const int OFF_AL = 128 * 128;        // 16 KB per A buffer
    const int OFF_BH = 2 * 128 * 128;
    const int OFF_BL = OFF_BH + D * 128;

    uint32_t sb = smem_u32(smem);
    int tid = threadIdx.x, wid = tid >> 5, lane = tid & 31;
    int wm = wid & 3, wn = wid >> 2;
    int row0 = wm * 32;
    int col0 = wn * WN;
    int grow = blockIdx.x * 128;

    float acc[2][NT][4];
#pragma unroll
    for (int i = 0; i < 2; i++)
#pragma unroll
        for (int j = 0; j < NT; j++)
#pragma unroll
            for (int q = 0; q < 4; q++) acc[i][j][q] = 0.f;

    for (int ch = 0; ch < NCH; ch++) {
        int kk = ch * CK;
        // ---- A chunk: 128 rows x 64 fp32 -> bf16 hi/lo swizzled
#pragma unroll
        for (int i = 0; i < 4; i++) {
            int u = tid + i * 256;
            int m = u >> 3, g = u & 7;
            int r = grow + m;
            float4 v0 = make_float4(0.f, 0.f, 0.f, 0.f), v1 = v0;
            if (r < NNODES) {
                const float* p = &A[(size_t)r * K + kk + g * 8];
                v0 = *(const float4*)p;
                v1 = *(const float4*)(p + 4);
            }
            if (RELU) {
                v0.x = fmaxf(v0.x, 0.f); v0.y = fmaxf(v0.y, 0.f);
                v0.z = fmaxf(v0.z, 0.f); v0.w = fmaxf(v0.w, 0.f);
                v1.x = fmaxf(v1.x, 0.f); v1.y = fmaxf(v1.y, 0.f);
                v1.z = fmaxf(v1.z, 0.f); v1.w = fmaxf(v1.w, 0.f);
            }
            float f[8] = {v0.x, v0.y, v0.z, v0.w, v1.x, v1.y, v1.z, v1.w};
            uint32_t hp[4], lp[4];
#pragma unroll
            for (int j = 0; j < 4; j++) {
                __nv_bfloat16 h0 = __float2bfloat16_rn(f[2 * j]);
                __nv_bfloat16 h1 = __float2bfloat16_rn(f[2 * j + 1]);
                __nv_bfloat16 l0 = __float2bfloat16_rn(f[2 * j] - __bfloat162float(h0));
                __nv_bfloat16 l1 = __float2bfloat16_rn(f[2 * j + 1] - __bfloat162float(h1));
                hp[j] = (uint32_t)__bfloat16_as_ushort(h0)
                      | ((uint32_t)__bfloat16_as_ushort(h1) << 16);
                lp[j] = (uint32_t)__bfloat16_as_ushort(l0)
                      | ((uint32_t)__bfloat16_as_ushort(l1) << 16);
            }
            uint32_t so = sw128((uint32_t)(m * 128 + g * 16));
            *(uint4*)(smem + OFF_AH + so) = make_uint4(hp[0], hp[1], hp[2], hp[3]);
            *(uint4*)(smem + OFF_AL + so) = make_uint4(lp[0], lp[1], lp[2], lp[3]);
        }
        // ---- B chunk: D rows x 64 bf16 (pre-split), swizzled
#pragma unroll
        for (int i = 0; i < (D * 8) / 256; i++) {
            int u = tid + i * 256;
            int n = u >> 3, g = u & 7;
            uint32_t so = sw128((uint32_t)(n * 128 + g * 16));
            *(uint4*)(smem + OFF_BH + so) = *(const uint4*)&Bh[n * K + kk + g * 8];
            *(uint4*)(smem + OFF_BL + so) = *(const uint4*)&Bl[n * K + kk + g * 8];
        }
        __syncthreads();
#pragma unroll
        for (int k16 = 0; k16 < CK / 16; k16++) {
            int kb = k16 * 32;               // byte offset of this k16 in row
            uint32_t ah[2][4], al[2][4];
#pragma unroll
            for (int mt = 0; mt < 2; mt++) {
                int r = row0 + mt * 16 + (lane & 15);
                int cb = kb + ((lane & 16) ? 16 : 0);
                uint32_t so = sw128((uint32_t)(r * 128 + cb));
                ldsm4(ah[mt], sb + OFF_AH + so);
                ldsm4(al[mt], sb + OFF_AL + so);
            }
#pragma unroll
            for (int bt = 0; bt < NT / 2; bt++) {
                int n = col0 + bt * 16 + (lane & 7) + ((lane & 16) ? 8 : 0);
                int cb = kb + ((lane & 8) ? 16 : 0);
                uint32_t so = sw128((uint32_t)(n * 128 + cb));
                uint32_t bh[4], bl[4];
                ldsm4(bh, sb + OFF_BH + so);
                ldsm4(bl, sb + OFF_BL + so);
#pragma unroll
                for (int h = 0; h < 2; h++) {
                    int nt = bt * 2 + h;
#pragma unroll
                    for (int mt = 0; mt < 2; mt++) {
                        mma16816(acc[mt][nt], ah[mt], &bh[h * 2]);
                        mma16816(acc[mt][nt], ah[mt], &bl[h * 2]);
                        mma16816(acc[mt][nt], al[mt], &bh[h * 2]);
                    }
                }
            }
        }
        __syncthreads();
    }
    // ---- epilogue: fragment -> global (float2 per store)
#pragma unroll
    for (int mt = 0; mt < 2; mt++) {
        int r0 = grow + row0 + mt * 16 + (lane >> 2);
        int r1 = r0 + 8;
#pragma unroll
        for (int nt = 0; nt < NT; nt++) {
            int cc = col0 + nt * 8 + (lane & 3) * 2;
            if (r0 < NNODES)
                *(float2*)&C[(size_t)r0 * D + cc] =
                    make_float2(acc[mt][nt][0], acc[mt][nt][1]);
            if (r1 < NNODES)
                *(float2*)&C[(size_t)r1 * D + cc] =
                    make_float2(acc[mt][nt][2], acc[mt][nt][3]);
        }
    }
}

// ---------------- sparse aggregation: out[i] = dinv[i]^2*t[i] + sum_e w*t[col]
__global__ void k_agg128(const float* __restrict__ tmp, float* __restrict__ out) {
    int gw = (blockIdx.x * blockDim.x + threadIdx.x) >> 5;
    int lane = threadIdx.x & 31;
    if (gw >= NNODES) return;
    const float4* __restrict__ t4 = (const float4*)tmp;
    float di = g_dinv[gw];
    float s = di * di;
    float4 v = t4[gw * 32 + lane];
    float4 acc = make_float4(v.x * s, v.y * s, v.z * s, v.w * s);
    float4 acc2 = make_float4(0.f, 0.f, 0.f, 0.f);
    int e = g_rowptr[gw], en = g_rowptr[gw + 1];
    for (; e + 1 < en; e += 2) {
        int c0 = g_col[e], c1 = g_col[e + 1];
        float w0 = g_w[e], w1 = g_w[e + 1];
        float4 u0 = t4[c0 * 32 + lane];
        float4 u1 = t4[c1 * 32 + lane];
        acc.x = fmaf(w0, u0.x, acc.x);   acc.y = fmaf(w0, u0.y, acc.y);
        acc.z = fmaf(w0, u0.z, acc.z);   acc.w = fmaf(w0, u0.w, acc.w);
        acc2.x = fmaf(w1, u1.x, acc2.x); acc2.y = fmaf(w1, u1.y, acc2.y);
        acc2.z = fmaf(w1, u1.z, acc2.z); acc2.w = fmaf(w1, u1.w, acc2.w);
    }
    if (e < en) {
        int c0 = g_col[e];
        float w0 = g_w[e];
        float4 u0 = t4[c0 * 32 + lane];
        acc.x = fmaf(w0, u0.x, acc.x); acc.y = fmaf(w0, u0.y, acc.y);
        acc.z = fmaf(w0, u0.z, acc.z); acc.w = fmaf(w0, u0.w, acc.w);
    }
    acc.x += acc2.x; acc.y += acc2.y; acc.z += acc2.z; acc.w += acc2.w;
    ((float4*)out)[gw * 32 + lane] = acc;
}

__global__ void k_agg64(const float* __restrict__ tmp, float* __restrict__ out) {
    int gw = (blockIdx.x * blockDim.x + threadIdx.x) >> 5;
    int lane = threadIdx.x & 31;
    if (gw >= NNODES) return;
    const float2* __restrict__ t2 = (const float2*)tmp;
    float di = g_dinv[gw];
    float s = di * di;
    float2 v = t2[gw * 32 + lane];
    float2 acc = make_float2(v.x * s, v.y * s);
    float2 acc2 = make_float2(0.f, 0.f);
    int e = g_rowptr[gw], en = g_rowptr[gw + 1];
    for (; e + 1 < en; e += 2) {
        int c0 = g_col[e], c1 = g_col[e + 1];
        float w0 = g_w[e], w1 = g_w[e + 1];
        float2 u0 = t2[c0 * 32 + lane];
        float2 u1 = t2[c1 * 32 + lane];
        acc.x = fmaf(w0, u0.x, acc.x);   acc.y = fmaf(w0, u0.y, acc.y);
        acc2.x = fmaf(w1, u1.x, acc2.x); acc2.y = fmaf(w1, u1.y, acc2.y);
    }
    if (e < en) {
        int c0 = g_col[e];
        float w0 = g_w[e];
        float2 u0 = t2[c0 * 32 + lane];
        acc.x = fmaf(w0, u0.x, acc.x); acc.y = fmaf(w0, u0.y, acc.y);
    }
    acc.x += acc2.x; acc.y += acc2.y;
    ((float2*)out)[gw * 32 + lane] = acc;
}

// ---------------- Gram matrix G = h^T h + column sums ----------------
template <int D>
__global__ void k_gram(const float* __restrict__ h) {
    const int RB = 8;
    const int TT = D / 16;
    __shared__ float srow[RB][D];
    int tid = threadIdx.x;
    int tx = tid & 15, ty = tid >> 4;

    float acc[TT][TT];
    float cs[TT];
#pragma unroll
    for (int i = 0; i < TT; i++) {
        cs[i] = 0.f;
#pragma unroll
        for (int j = 0; j < TT; j++) acc[i][j] = 0.f;
    }

    for (int r0 = blockIdx.x * RB; r0 < NNODES; r0 += gridDim.x * RB) {
        int nr = NNODES - r0; if (nr > RB) nr = RB;
        for (int idx = tid; idx < nr * D; idx += 256)
            srow[idx / D][idx % D] = h[(r0 + idx / D) * D + idx % D];
        __syncthreads();
        for (int rr = 0; rr < nr; rr++) {
            float a[TT], b[TT];
#pragma unroll
            for (int i = 0; i < TT; i++) {
                a[i] = srow[rr][ty * TT + i];
                b[i] = srow[rr][tx * TT + i];
            }
#pragma unroll
            for (int i = 0; i < TT; i++)
#pragma unroll
                for (int j = 0; j < TT; j++) acc[i][j] = fmaf(a[i], b[j], acc[i][j]);
            if (ty == 0)
#pragma unroll
                for (int j = 0; j < TT; j++) cs[j] += b[j];
        }
        __syncthreads();
    }
#pragma unroll
    for (int i = 0; i < TT; i++)
#pragma unroll
        for (int j = 0; j < TT; j++)
            atomicAdd(&g_G[(ty * TT + i) * D + tx * TT + j], acc[i][j]);
    if (ty == 0)
#pragma unroll
        for (int j = 0; j < TT; j++) atomicAdd(&g_csum[tx * TT + j], cs[j]);
}

// ---------------- correlation metric finalize (single block) ----------------
template <int D>
__global__ void k_finalize(float* __restrict__ dst) {
    __shared__ float sd[D];
    __shared__ float red[256];
    int tid = threadIdx.x;
    const float invN = 1.0f / (float)NNODES;
    if (tid < D) {
        float cjj = g_G[tid * D + tid] - g_csum[tid] * g_csum[tid] * invN;
        sd[tid] = sqrtf(fmaxf(cjj, 1e-12f));
    }
    __syncthreads();
    float sum = 0.f;
    for (int idx = tid; idx < D * D; idx += 256) {
        int j = idx / D, k = idx % D;
        if (k > j) {
            float cov = g_G[idx] - g_csum[j] * g_csum[k] * invN;
            sum += fabsf(cov / (sd[j] * sd[k]));
        }
    }
    red[tid] = sum;
    __syncthreads();
    for (int off = 128; off > 0; off >>= 1) {
        if (tid < off) red[tid] += red[tid + off];
        __syncthreads();
    }
    if (tid == 0) *dst = red[0] / (float)(D * (D - 1) / 2);
}

// ---------------- launch ----------------
extern "C" void kernel_launch(void* const* d_in, const int* in_sizes, int n_in,
                              void* d_out, int out_size) {
    const float* x  = (const float*)d_in[0];
    const int*   ei = (const int*)d_in[1];
    const float* W0 = (const float*)d_in[2];
    const float* W1 = (const float*)d_in[3];
    const float* W2 = (const float*)d_in[4];
    const float* W3 = (const float*)d_in[5];
    float* out = (float*)d_out;

    float *buf0, *buf1;
    cudaGetSymbolAddress((void**)&buf0, g_buf0);
    cudaGetSymbolAddress((void**)&buf1, g_buf1);
    __nv_bfloat16 *w0h, *w0l, *w1h, *w1l, *w2h, *w2l, *w3h, *w3l;
    cudaGetSymbolAddress((void**)&w0h, g_w0h); cudaGetSymbolAddress((void**)&w0l, g_w0l);
    cudaGetSymbolAddress((void**)&w1h, g_w1h); cudaGetSymbolAddress((void**)&w1l, g_w1l);
    cudaGetSymbolAddress((void**)&w2h, g_w2h); cudaGetSymbolAddress((void**)&w2l, g_w2l);
    cudaGetSymbolAddress((void**)&w3h, g_w3h); cudaGetSymbolAddress((void**)&w3l, g_w3l);

    const int SM_BIG = 2 * 128 * 128 + 2 * HID * 128;   // 65536
    const int SM_SML = 2 * 128 * 128 + 2 * COUT * 128;  // 49152
    cudaFuncSetAttribute(k_tgemm<FIN, HID, false>,
                         cudaFuncAttributeMaxDynamicSharedMemorySize, SM_BIG);
    cudaFuncSetAttribute(k_tgemm<HID, HID, true>,
                         cudaFuncAttributeMaxDynamicSharedMemorySize, SM_BIG);
    cudaFuncSetAttribute(k_tgemm<HID, COUT, true>,
                         cudaFuncAttributeMaxDynamicSharedMemorySize, SM_SML);

    const int TB = 256;
    const int nbN = (NNODES + TB - 1) / TB;
    const int nbE = (NEDGES + TB - 1) / TB;
    const int nbM = (NNODES + 127) / 128;        // GEMM blocks (128 rows)
    const int nbA = (NNODES + 7) / 8;            // agg blocks (8 warps/block)

    // preprocessing: degrees, dinv, CSR, weight split
    k_zero_init<<<nbN, TB>>>();
    k_count<<<nbE, TB>>>(ei);
    k_dinv<<<nbN, TB>>>();
    k_scan1<<<SCAN_NB, SCAN_TPB>>>();
    k_scan2<<<1, 64>>>();
    k_scan3<<<SCAN_NB, SCAN_TPB>>>();
    k_fill<<<nbE, TB>>>(ei);
    k_prepW<FIN, HID><<<(FIN * HID + TB - 1) / TB, TB>>>(W0, w0h, w0l);
    k_prepW<HID, HID><<<(HID * HID + TB - 1) / TB, TB>>>(W1, w1h, w1l);
    k_prepW<HID, HID><<<(HID * HID + TB - 1) / TB, TB>>>(W2, w2h, w2l);
    k_prepW<HID, COUT><<<(HID * COUT + TB - 1) / TB, TB>>>(W3, w3h, w3l);

    // layer 0: x[N,256] @ W0 -> agg
    k_tgemm<FIN, HID, false><<<nbM, 256, SM_BIG>>>(x, w0h, w0l, buf0);
    k_agg128<<<nbA, TB>>>(buf0, buf1);
    // layer 1: relu(h0) @ W1 -> agg
    k_tgemm<HID, HID, true><<<nbM, 256, SM_BIG>>>(buf1, w1h, w1l, buf0);
    k_agg128<<<nbA, TB>>>(buf0, buf1);
    // layer 2: relu(h1) @ W2 -> agg (corr_2 on h2)
    k_tgemm<HID, HID, true><<<nbM, 256, SM_BIG>>>(buf1, w2h, w2l, buf0);
    k_agg128<<<nbA, TB>>>(buf0, buf1);

    // corr_2 metric on h2
    k_zero_G<<<(HID * HID + TB - 1) / TB, TB>>>();
    k_gram<HID><<<296, TB>>>(buf1);
    k_finalize<HID><<<1, TB>>>(out + NNODES * COUT);

    // layer 3: relu(h2) @ W3 -> agg directly into d_out
    k_tgemm<HID, COUT, true><<<nbM, 256, SM_SML>>>(buf1, w3h, w3l, buf0);
    k_agg64<<<nbA, TB>>>(buf0, out);

    // corr metric on h3
    k_zero_G<<<(HID * HID + TB - 1) / TB, TB>>>();
    k_gram<COUT><<<296, TB>>>(out);
    k_finalize<COUT><<<1, TB>>>(out + NNODES * COUT + 1);
}

// round 5
// speedup vs baseline: 1.5703x; 1.1740x over previous
#include <cuda_runtime.h>
#include <cuda_bf16.h>
#include <cuda_fp16.h>
#include <math.h>
#include <stdint.h>

#define NNODES 100000
#define NEDGES 1600000
#define FIN 256
#define HID 128
#define COUT 64

#define SCAN_TPB 256
#define SCAN_ELEMS 8
#define SCAN_CHUNK (SCAN_TPB * SCAN_ELEMS)                 // 2048
#define SCAN_NB ((NNODES + SCAN_CHUNK - 1) / SCAN_CHUNK)   // 49

// ---------------- scratch (static __device__, no allocation) ----------------
__device__ __half g_tmp[NNODES * HID];   // GEMM output (pre-aggregation), fp16
__device__ float g_buf1[NNODES * HID];   // aggregated h (layer output), fp32
__device__ float g_dinv[NNODES];
__device__ int   g_cnt[NNODES];
__device__ int   g_cursor[NNODES];
__device__ int   g_rowptr[NNODES + 1];
__device__ int   g_col[NEDGES];
__device__ float g_w[NEDGES];
__device__ float g_G[HID * HID];
__device__ float g_csum[HID];
__device__ int   g_bsum[SCAN_NB];

// split-bf16 transposed weights: Wt[d][k] = W[k][d]
__device__ __nv_bfloat16 g_w0h[HID * FIN],  g_w0l[HID * FIN];
__device__ __nv_bfloat16 g_w1h[HID * HID],  g_w1l[HID * HID];
__device__ __nv_bfloat16 g_w2h[HID * HID],  g_w2l[HID * HID];
__device__ __nv_bfloat16 g_w3h[COUT * HID], g_w3l[COUT * HID];

// ---------------- helpers ----------------
__device__ __forceinline__ uint32_t smem_u32(const void* p) {
    uint32_t a;
    asm("{ .reg .u64 t; cvta.to.shared.u64 t, %1; cvt.u32.u64 %0, t; }"
        : "=r"(a) : "l"(p));
    return a;
}
__device__ __forceinline__ uint32_t sw128(uint32_t off) {
    return off ^ ((off >> 3) & 0x70);
}
__device__ __forceinline__ void ldsm4(uint32_t* r, uint32_t addr) {
    asm volatile("ldmatrix.sync.aligned.m8n8.x4.shared.b16 {%0,%1,%2,%3}, [%4];"
                 : "=r"(r[0]), "=r"(r[1]), "=r"(r[2]), "=r"(r[3]) : "r"(addr));
}
__device__ __forceinline__ void mma16816(float* c, const uint32_t* a,
                                         const uint32_t* b) {
    asm volatile(
        "mma.sync.aligned.m16n8k16.row.col.f32.bf16.bf16.f32 "
        "{%0,%1,%2,%3}, {%4,%5,%6,%7}, {%8,%9}, {%0,%1,%2,%3};"
        : "+f"(c[0]), "+f"(c[1]), "+f"(c[2]), "+f"(c[3])
        : "r"(a[0]), "r"(a[1]), "r"(a[2]), "r"(a[3]), "r"(b[0]), "r"(b[1]));
}
__device__ __forceinline__ uint32_t pack_bf16(float a, float b) {
    __nv_bfloat16 x = __float2bfloat16_rn(a);
    __nv_bfloat16 y = __float2bfloat16_rn(b);
    return (uint32_t)__bfloat16_as_ushort(x)
         | ((uint32_t)__bfloat16_as_ushort(y) << 16);
}

// ---------------- preprocessing ----------------
__global__ void k_zero_init() {
    int i = blockIdx.x * blockDim.x + threadIdx.x;
    if (i < NNODES) { g_cnt[i] = 0; g_cursor[i] = 0; }
}

__global__ void k_zero_G() {
    int i = blockIdx.x * blockDim.x + threadIdx.x;
    if (i < HID * HID) g_G[i] = 0.f;
    if (i < HID) g_csum[i] = 0.f;
}

__global__ void k_count(const int* __restrict__ ei) {
    int e = blockIdx.x * blockDim.x + threadIdx.x;
    if (e < NEDGES) atomicAdd(&g_cnt[ei[e]], 1);
}

__global__ void k_dinv() {
    int i = blockIdx.x * blockDim.x + threadIdx.x;
    if (i < NNODES) g_dinv[i] = rsqrtf((float)(g_cnt[i] + 1));  // +1 self loop
}

__global__ void k_scan1() {
    __shared__ int warp_s[SCAN_TPB / 32];
    int tid = threadIdx.x, blk = blockIdx.x;
    int base = blk * SCAN_CHUNK + tid * SCAN_ELEMS;
    int s = 0;
#pragma unroll
    for (int i = 0; i < SCAN_ELEMS; i++) {
        int idx = base + i;
        if (idx < NNODES) s += g_cnt[idx];
    }
    for (int o = 16; o > 0; o >>= 1) s += __shfl_down_sync(0xffffffffu, s, o);
    if ((tid & 31) == 0) warp_s[tid >> 5] = s;
    __syncthreads();
    if (tid < SCAN_TPB / 32) {
        int w = warp_s[tid];
        for (int o = (SCAN_TPB / 64); o > 0; o >>= 1)
            w += __shfl_down_sync(0xffu, w, o);
        if (tid == 0) g_bsum[blk] = w;
    }
}

__global__ void k_scan2() {
    __shared__ int sh[64];
    int tid = threadIdx.x;
    sh[tid] = (tid < SCAN_NB) ? g_bsum[tid] : 0;
    __syncthreads();
    for (int o = 1; o < 64; o <<= 1) {
        int v = (tid >= o) ? sh[tid - o] : 0;
        __syncthreads();
        sh[tid] += v;
        __syncthreads();
    }
    if (tid < SCAN_NB) g_bsum[tid] = (tid == 0) ? 0 : sh[tid - 1];
    if (tid == 0) g_rowptr[NNODES] = sh[SCAN_NB - 1];
}

__global__ void k_scan3() {
    __shared__ int tsum[SCAN_TPB];
    int tid = threadIdx.x, blk = blockIdx.x;
    int base = blk * SCAN_CHUNK + tid * SCAN_ELEMS;
    int c[SCAN_ELEMS];
    int s = 0;
#pragma unroll
    for (int i = 0; i < SCAN_ELEMS; i++) {
        int idx = base + i;
        c[i] = (idx < NNODES) ? g_cnt[idx] : 0;
        s += c[i];
    }
    tsum[tid] = s;
    __syncthreads();
    for (int o = 1; o < SCAN_TPB; o <<= 1) {
        int v = (tid >= o) ? tsum[tid - o] : 0;
        __syncthreads();
        tsum[tid] += v;
        __syncthreads();
    }
    int run = g_bsum[blk] + ((tid == 0) ? 0 : tsum[tid - 1]);
#pragma unroll
    for (int i = 0; i < SCAN_ELEMS; i++) {
        int idx = base + i;
        if (idx < NNODES) { g_rowptr[idx] = run; run += c[i]; }
    }
}

__global__ void k_fill(const int* __restrict__ ei) {
    int e = blockIdx.x * blockDim.x + threadIdx.x;
    if (e >= NEDGES) return;
    int r = ei[e];
    int c = ei[NEDGES + e];
    int pos = g_rowptr[r] + atomicAdd(&g_cursor[r], 1);
    g_col[pos] = c;
    g_w[pos] = g_dinv[r] * g_dinv[c];
}

// ---------------- weight prep: W[K,D] fp32 -> Wt hi/lo bf16 [D][K] ----------
template <int K, int D>
__global__ void k_prepW(const float* __restrict__ W,
                        __nv_bfloat16* __restrict__ Wh,
                        __nv_bfloat16* __restrict__ Wl) {
    int i = blockIdx.x * blockDim.x + threadIdx.x;
    if (i >= K * D) return;
    int n = i / K, k = i % K;
    float v = W[k * D + n];
    __nv_bfloat16 h = __float2bfloat16_rn(v);
    __nv_bfloat16 l = __float2bfloat16_rn(v - __bfloat162float(h));
    Wh[n * K + k] = h;
    Wl[n * K + k] = l;
}

// ---------------- tensor-core split-bf16 GEMM: C = act(A[N,K]) @ W[K,D] ----
// CTA: 128 rows x D cols, 256 threads (8 warps as 4x2). Warp tile 32 x D/2.
// K chunked by 64 into SW128-swizzled smem (128B rows); mma.sync m16n8k16.
// Output written as fp16 (consumed only by the gather-bound aggregation).
template <int K, int D, bool RELU>
__global__ __launch_bounds__(256) void k_tgemm(const float* __restrict__ A,
                                               const __nv_bfloat16* __restrict__ Bh,
                                               const __nv_bfloat16* __restrict__ Bl,
                                               __half* __restrict__ C) {
    extern __shared__ __align__(1024) uint8_t smem[];
    const int CK = 64;                   // K elems per chunk
    const int NCH = K / CK;
    const int WN = D / 2;                // 64 or 32
    const int NT = WN / 8;               // 8 or 4 n8-tiles per warp
    const int OFF_AH = 0;
    const int OFF_AL = 128 * 128;        // 16 KB per A buffer
    const int OFF_BH = 2 * 128 * 128;
    const int OFF_BL = OFF_BH + D * 128;

    uint32_t sb = smem_u32(smem);
    int tid = threadIdx.x, wid = tid >> 5, lane = tid & 31;
    int wm = wid & 3, wn = wid >> 2;
    int row0 = wm * 32;
    int col0 = wn * WN;
    int grow = blockIdx.x * 128;

    float acc[2][NT][4];
#pragma unroll
    for (int i = 0; i < 2; i++)
#pragma unroll
        for (int j = 0; j < NT; j++)
#pragma unroll
            for (int q = 0; q < 4; q++) acc[i][j][q] = 0.f;

    for (int ch = 0; ch < NCH; ch++) {
        int kk = ch * CK;
        // ---- A chunk: 128 rows x 64 fp32 -> bf16 hi/lo swizzled
#pragma unroll
        for (int i = 0; i < 4; i++) {
            int u = tid + i * 256;
            int m = u >> 3, g = u & 7;
            int r = grow + m;
            float4 v0 = make_float4(0.f, 0.f, 0.f, 0.f), v1 = v0;
            if (r < NNODES) {
                const float* p = &A[(size_t)r * K + kk + g * 8];
                v0 = *(const float4*)p;
                v1 = *(const float4*)(p + 4);
            }
            if (RELU) {
                v0.x = fmaxf(v0.x, 0.f); v0.y = fmaxf(v0.y, 0.f);
                v0.z = fmaxf(v0.z, 0.f); v0.w = fmaxf(v0.w, 0.f);
                v1.x = fmaxf(v1.x, 0.f); v1.y = fmaxf(v1.y, 0.f);
                v1.z = fmaxf(v1.z, 0.f); v1.w = fmaxf(v1.w, 0.f);
            }
            float f[8] = {v0.x, v0.y, v0.z, v0.w, v1.x, v1.y, v1.z, v1.w};
            uint32_t hp[4], lp[4];
#pragma unroll
            for (int j = 0; j < 4; j++) {
                __nv_bfloat16 h0 = __float2bfloat16_rn(f[2 * j]);
                __nv_bfloat16 h1 = __float2bfloat16_rn(f[2 * j + 1]);
                __nv_bfloat16 l0 = __float2bfloat16_rn(f[2 * j] - __bfloat162float(h0));
                __nv_bfloat16 l1 = __float2bfloat16_rn(f[2 * j + 1] - __bfloat162float(h1));
                hp[j] = (uint32_t)__bfloat16_as_ushort(h0)
                      | ((uint32_t)__bfloat16_as_ushort(h1) << 16);
                lp[j] = (uint32_t)__bfloat16_as_ushort(l0)
                      | ((uint32_t)__bfloat16_as_ushort(l1) << 16);
            }
            uint32_t so = sw128((uint32_t)(m * 128 + g * 16));
            *(uint4*)(smem + OFF_AH + so) = make_uint4(hp[0], hp[1], hp[2], hp[3]);
            *(uint4*)(smem + OFF_AL + so) = make_uint4(lp[0], lp[1], lp[2], lp[3]);
        }
        // ---- B chunk: D rows x 64 bf16 (pre-split), swizzled
#pragma unroll
        for (int i = 0; i < (D * 8) / 256; i++) {
            int u = tid + i * 256;
            int n = u >> 3, g = u & 7;
            uint32_t so = sw128((uint32_t)(n * 128 + g * 16));
            *(uint4*)(smem + OFF_BH + so) = *(const uint4*)&Bh[n * K + kk + g * 8];
            *(uint4*)(smem + OFF_BL + so) = *(const uint4*)&Bl[n * K + kk + g * 8];
        }
        __syncthreads();
#pragma unroll
        for (int k16 = 0; k16 < CK / 16; k16++) {
            int kb = k16 * 32;               // byte offset of this k16 in row
            uint32_t ah[2][4], al[2][4];
#pragma unroll
            for (int mt = 0; mt < 2; mt++) {
                int r = row0 + mt * 16 + (lane & 15);
                int cb = kb + ((lane & 16) ? 16 : 0);
                uint32_t so = sw128((uint32_t)(r * 128 + cb));
                ldsm4(ah[mt], sb + OFF_AH + so);
                ldsm4(al[mt], sb + OFF_AL + so);
            }
#pragma unroll
            for (int bt = 0; bt < NT / 2; bt++) {
                int n = col0 + bt * 16 + (lane & 7) + ((lane & 16) ? 8 : 0);
                int cb = kb + ((lane & 8) ? 16 : 0);
                uint32_t so = sw128((uint32_t)(n * 128 + cb));
                uint32_t bh[4], bl[4];
                ldsm4(bh, sb + OFF_BH + so);
                ldsm4(bl, sb + OFF_BL + so);
#pragma unroll
                for (int h = 0; h < 2; h++) {
                    int nt = bt * 2 + h;
#pragma unroll
                    for (int mt = 0; mt < 2; mt++) {
                        mma16816(acc[mt][nt], ah[mt], &bh[h * 2]);
                        mma16816(acc[mt][nt], ah[mt], &bl[h * 2]);
                        mma16816(acc[mt][nt], al[mt], &bh[h * 2]);
                    }
                }
            }
        }
        __syncthreads();
    }
    // ---- epilogue: fragment -> global fp16 (half2 per store)
#pragma unroll
    for (int mt = 0; mt < 2; mt++) {
        int r0 = grow + row0 + mt * 16 + (lane >> 2);
        int r1 = r0 + 8;
#pragma unroll
        for (int nt = 0; nt < NT; nt++) {
            int cc = col0 + nt * 8 + (lane & 3) * 2;
            if (r0 < NNODES)
                *(__half2*)&C[(size_t)r0 * D + cc] =
                    __floats2half2_rn(acc[mt][nt][0], acc[mt][nt][1]);
            if (r1 < NNODES)
                *(__half2*)&C[(size_t)r1 * D + cc] =
                    __floats2half2_rn(acc[mt][nt][2], acc[mt][nt][3]);
        }
    }
}

// ---------------- sparse aggregation (fp16 gather, fp32 accumulate) --------
// out[i] = dinv[i]^2 * tmp[i] + sum_e w_e * tmp[col_e]
__global__ void k_agg128h(const __half* __restrict__ tmp, float* __restrict__ out) {
    int gw = (blockIdx.x * blockDim.x + threadIdx.x) >> 5;
    int lane = threadIdx.x & 31;
    if (gw >= NNODES) return;
    const uint2* __restrict__ t = (const uint2*)tmp;   // 4 halves per lane
    float di = g_dinv[gw];
    float s = di * di;
    uint2 u = t[gw * 32 + lane];
    float2 p0 = __half22float2(*(__half2*)&u.x);
    float2 p1 = __half22float2(*(__half2*)&u.y);
    float4 acc = make_float4(p0.x * s, p0.y * s, p1.x * s, p1.y * s);
    float4 acc2 = make_float4(0.f, 0.f, 0.f, 0.f);
    int e = g_rowptr[gw], en = g_rowptr[gw + 1];
    for (; e + 1 < en; e += 2) {
        int c0 = g_col[e], c1 = g_col[e + 1];
        float w0 = g_w[e], w1 = g_w[e + 1];
        uint2 a = t[c0 * 32 + lane];
        uint2 b = t[c1 * 32 + lane];
        float2 a0 = __half22float2(*(__half2*)&a.x);
        float2 a1 = __half22float2(*(__half2*)&a.y);
        float2 b0 = __half22float2(*(__half2*)&b.x);
        float2 b1 = __half22float2(*(__half2*)&b.y);
        acc.x = fmaf(w0, a0.x, acc.x);   acc.y = fmaf(w0, a0.y, acc.y);
        acc.z = fmaf(w0, a1.x, acc.z);   acc.w = fmaf(w0, a1.y, acc.w);
        acc2.x = fmaf(w1, b0.x, acc2.x); acc2.y = fmaf(w1, b0.y, acc2.y);
        acc2.z = fmaf(w1, b1.x, acc2.z); acc2.w = fmaf(w1, b1.y, acc2.w);
    }
    if (e < en) {
        int c0 = g_col[e];
        float w0 = g_w[e];
        uint2 a = t[c0 * 32 + lane];
        float2 a0 = __half22float2(*(__half2*)&a.x);
        float2 a1 = __half22float2(*(__half2*)&a.y);
        acc.x = fmaf(w0, a0.x, acc.x); acc.y = fmaf(w0, a0.y, acc.y);
        acc.z = fmaf(w0, a1.x, acc.z); acc.w = fmaf(w0, a1.y, acc.w);
    }
    acc.x += acc2.x; acc.y += acc2.y; acc.z += acc2.z; acc.w += acc2.w;
    ((float4*)out)[gw * 32 + lane] = acc;
}

__global__ void k_agg64h(const __half* __restrict__ tmp, float* __restrict__ out) {
    int gw = (blockIdx.x * blockDim.x + threadIdx.x) >> 5;
    int lane = threadIdx.x & 31;
    if (gw >= NNODES) return;
    const uint32_t* __restrict__ t = (const uint32_t*)tmp;  // 2 halves per lane
    float di = g_dinv[gw];
    float s = di * di;
    uint32_t u = t[gw * 32 + lane];
    float2 p = __half22float2(*(__half2*)&u);
    float2 acc = make_float2(p.x * s, p.y * s);
    float2 acc2 = make_float2(0.f, 0.f);
    int e = g_rowptr[gw], en = g_rowptr[gw + 1];
    for (; e + 1 < en; e += 2) {
        int c0 = g_col[e], c1 = g_col[e + 1];
        float w0 = g_w[e], w1 = g_w[e + 1];
        uint32_t a = t[c0 * 32 + lane];
        uint32_t b = t[c1 * 32 + lane];
        float2 af = __half22float2(*(__half2*)&a);
        float2 bf = __half22float2(*(__half2*)&b);
        acc.x = fmaf(w0, af.x, acc.x);   acc.y = fmaf(w0, af.y, acc.y);
        acc2.x = fmaf(w1, bf.x, acc2.x); acc2.y = fmaf(w1, bf.y, acc2.y);
    }
    if (e < en) {
        int c0 = g_col[e];
        float w0 = g_w[e];
        uint32_t a = t[c0 * 32 + lane];
        float2 af = __half22float2(*(__half2*)&a);
        acc.x = fmaf(w0, af.x, acc.x); acc.y = fmaf(w0, af.y, acc.y);
    }
    acc.x += acc2.x; acc.y += acc2.y;
    ((float2*)out)[gw * 32 + lane] = acc;
}

// ---------------- Gram via mma: G = H^T H (split-bf16), csum fused ----------
// Per 64-row chunk: convert H[rows][D] fp32 -> transposed bf16 hi/lo smem
// tile Tt[feat][row] (128B rows = one SW128 atom), then the SAME tile serves
// as both A (m=feat) and B (n=feat) operands of m16n8k16.
template <int D>
__global__ __launch_bounds__(256) void k_gram_mma(const float* __restrict__ h) {
    __shared__ __align__(1024) uint8_t sm[2 * D * 128];
    const int OFF_L = D * 128;
    const int FG = D / 4;            // threads per row-pair (feature groups)
    const int PAIRS = 256 / FG;      // row-pairs per pass
    const int NT = D / 8;            // n8 tiles per compute warp
    const int MW = D / 16;           // compute warps
    uint32_t sb = smem_u32(sm);
    int tid = threadIdx.x, wid = tid >> 5, lane = tid & 31;
    int f4 = tid % FG;               // this thread's feature group (4 feats)
    int rp0 = tid / FG;              // row-pair slot

    float acc[NT][4];
#pragma unroll
    for (int j = 0; j < NT; j++)
#pragma unroll
        for (int q = 0; q < 4; q++) acc[j][q] = 0.f;
    float cs0 = 0.f, cs1 = 0.f, cs2 = 0.f, cs3 = 0.f;

    const int NCHUNK = (NNODES + 63) / 64;
    for (int ch = blockIdx.x; ch < NCHUNK; ch += gridDim.x) {
        int rbase = ch * 64;
        // ---- load 64 rows, convert, transpose-store (2 rows packed per u32)
#pragma unroll
        for (int it = 0; it < 32 / PAIRS; it++) {
            int pr = rp0 + it * PAIRS;           // pair index 0..31
            int r0 = rbase + pr * 2, r1 = r0 + 1;
            float4 v0 = make_float4(0.f, 0.f, 0.f, 0.f), v1 = v0;
            if (r0 < NNODES) v0 = *(const float4*)&h[(size_t)r0 * D + f4 * 4];
            if (r1 < NNODES) v1 = *(const float4*)&h[(size_t)r1 * D + f4 * 4];
            cs0 += v0.x + v1.x; cs1 += v0.y + v1.y;
            cs2 += v0.z + v1.z; cs3 += v0.w + v1.w;
            float a0[4] = {v0.x, v0.y, v0.z, v0.w};
            float a1[4] = {v1.x, v1.y, v1.z, v1.w};
#pragma unroll
            for (int j = 0; j < 4; j++) {
                int feat = f4 * 4 + j;
                __nv_bfloat16 h0 = __float2bfloat16_rn(a0[j]);
                __nv_bfloat16 h1 = __float2bfloat16_rn(a1[j]);
                uint32_t hp = (uint32_t)__bfloat16_as_ushort(h0)
                            | ((uint32_t)__bfloat16_as_ushort(h1) << 16);
                uint32_t lp = pack_bf16(a0[j] - __bfloat162float(h0),
                                        a1[j] - __bfloat162float(h1));
                uint32_t so = sw128((uint32_t)(feat * 128 + pr * 4));
                *(uint32_t*)(sm + so) = hp;
                *(uint32_t*)(sm + OFF_L + so) = lp;
            }
        }
        __syncthreads();
        if (wid < MW) {
#pragma unroll
            for (int k16 = 0; k16 < 4; k16++) {
                int kb = k16 * 32;
                uint32_t ah[4], al[4];
                {
                    int r = wid * 16 + (lane & 15);
                    int cb = kb + ((lane & 16) ? 16 : 0);
                    uint32_t so = sw128((uint32_t)(r * 128 + cb));
                    ldsm4(ah, sb + so);
                    ldsm4(al, sb + OFF_L + so);
                }
#pragma unroll
                for (int bt = 0; bt < NT / 2; bt++) {
                    int n = bt * 16 + (lane & 7) + ((lane & 16) ? 8 : 0);
                    int cb = kb + ((lane & 8) ? 16 : 0);
                    uint32_t so = sw128((uint32_t)(n * 128 + cb));
                    uint32_t bh[4], bl[4];
                    ldsm4(bh, sb + so);
                    ldsm4(bl, sb + OFF_L + so);
#pragma unroll
                    for (int hh = 0; hh < 2; hh++) {
                        int nt = bt * 2 + hh;
                        mma16816(acc[nt], ah, &bh[hh * 2]);
                        mma16816(acc[nt], ah, &bl[hh * 2]);
                        mma16816(acc[nt], al, &bh[hh * 2]);
                    }
                }
            }
        }
        __syncthreads();
    }
    // ---- reduce fragments into g_G
    if (wid < MW) {
        int mrow = wid * 16 + (lane >> 2);
#pragma unroll
        for (int nt = 0; nt < NT; nt++) {
            int c = nt * 8 + (lane & 3) * 2;
            atomicAdd(&g_G[mrow * D + c], acc[nt][0]);
            atomicAdd(&g_G[mrow * D + c + 1], acc[nt][1]);
            atomicAdd(&g_G[(mrow + 8) * D + c], acc[nt][2]);
            atomicAdd(&g_G[(mrow + 8) * D + c + 1], acc[nt][3]);
        }
    }
    atomicAdd(&g_csum[f4 * 4 + 0], cs0);
    atomicAdd(&g_csum[f4 * 4 + 1], cs1);
    atomicAdd(&g_csum[f4 * 4 + 2], cs2);
    atomicAdd(&g_csum[f4 * 4 + 3], cs3);
}

// ---------------- correlation metric finalize (single block) ----------------
template <int D>
__global__ void k_finalize(float* __restrict__ dst) {
    __shared__ float sd[D];
    __shared__ float red[256];
    int tid = threadIdx.x;
    const float invN = 1.0f / (float)NNODES;
    if (tid < D) {
        float cjj = g_G[tid * D + tid] - g_csum[tid] * g_csum[tid] * invN;
        sd[tid] = sqrtf(fmaxf(cjj, 1e-12f));
    }
    __syncthreads();
    float sum = 0.f;
    for (int idx = tid; idx < D * D; idx += 256) {
        int j = idx / D, k = idx % D;
        if (k > j) {
            float cov = g_G[idx] - g_csum[j] * g_csum[k] * invN;
            sum += fabsf(cov / (sd[j] * sd[k]));
        }
    }
    red[tid] = sum;
    __syncthreads();
    for (int off = 128; off > 0; off >>= 1) {
        if (tid < off) red[tid] += red[tid + off];
        __syncthreads();
    }
    if (tid == 0) *dst = red[0] / (float)(D * (D - 1) / 2);
}

// ---------------- launch ----------------
extern "C" void kernel_launch(void* const* d_in, const int* in_sizes, int n_in,
                              void* d_out, int out_size) {
    const float* x  = (const float*)d_in[0];
    const int*   ei = (const int*)d_in[1];
    const float* W0 = (const float*)d_in[2];
    const float* W1 = (const float*)d_in[3];
    const float* W2 = (const float*)d_in[4];
    const float* W3 = (const float*)d_in[5];
    float* out = (float*)d_out;

    float* buf1;
    __half* tmp;
    cudaGetSymbolAddress((void**)&buf1, g_buf1);
    cudaGetSymbolAddress((void**)&tmp, g_tmp);
    __nv_bfloat16 *w0h, *w0l, *w1h, *w1l, *w2h, *w2l, *w3h, *w3l;
    cudaGetSymbolAddress((void**)&w0h, g_w0h); cudaGetSymbolAddress((void**)&w0l, g_w0l);
    cudaGetSymbolAddress((void**)&w1h, g_w1h); cudaGetSymbolAddress((void**)&w1l, g_w1l);
    cudaGetSymbolAddress((void**)&w2h, g_w2h); cudaGetSymbolAddress((void**)&w2l, g_w2l);
    cudaGetSymbolAddress((void**)&w3h, g_w3h); cudaGetSymbolAddress((void**)&w3l, g_w3l);

    const int SM_BIG = 2 * 128 * 128 + 2 * HID * 128;   // 65536
    const int SM_SML = 2 * 128 * 128 + 2 * COUT * 128;  // 49152
    cudaFuncSetAttribute(k_tgemm<FIN, HID, false>,
                         cudaFuncAttributeMaxDynamicSharedMemorySize, SM_BIG);
    cudaFuncSetAttribute(k_tgemm<HID, HID, true>,
                         cudaFuncAttributeMaxDynamicSharedMemorySize, SM_BIG);
    cudaFuncSetAttribute(k_tgemm<HID, COUT, true>,
                         cudaFuncAttributeMaxDynamicSharedMemorySize, SM_SML);

    const int TB = 256;
    const int nbN = (NNODES + TB - 1) / TB;
    const int nbE = (NEDGES + TB - 1) / TB;
    const int nbM = (NNODES + 127) / 128;        // GEMM blocks (128 rows)
    const int nbA = (NNODES + 7) / 8;            // agg blocks (8 warps/block)

    // Launch order arranged so the layer-0 GEMM is launch index 3 (the one
    // ncu's -s/-c window captures), while preserving dependencies.
    k_prepW<FIN, HID><<<(FIN * HID + TB - 1) / TB, TB>>>(W0, w0h, w0l);   // 0
    k_zero_init<<<nbN, TB>>>();                                            // 1
    k_count<<<nbE, TB>>>(ei);                                              // 2
    k_tgemm<FIN, HID, false><<<nbM, 256, SM_BIG>>>(x, w0h, w0l, tmp);      // 3
    k_dinv<<<nbN, TB>>>();                                                 // 4
    k_scan1<<<SCAN_NB, SCAN_TPB>>>();                                      // 5
    k_scan2<<<1, 64>>>();                                                  // 6
    k_scan3<<<SCAN_NB, SCAN_TPB>>>();                                      // 7
    k_fill<<<nbE, TB>>>(ei);                                               // 8
    k_prepW<HID, HID><<<(HID * HID + TB - 1) / TB, TB>>>(W1, w1h, w1l);
    k_prepW<HID, HID><<<(HID * HID + TB - 1) / TB, TB>>>(W2, w2h, w2l);
    k_prepW<HID, COUT><<<(HID * COUT + TB - 1) / TB, TB>>>(W3, w3h, w3l);

    // layer 0 aggregation
    k_agg128h<<<nbA, TB>>>(tmp, buf1);
    // layer 1
    k_tgemm<HID, HID, true><<<nbM, 256, SM_BIG>>>(buf1, w1h, w1l, tmp);
    k_agg128h<<<nbA, TB>>>(tmp, buf1);
    // layer 2 (corr_2 on h2)
    k_tgemm<HID, HID, true><<<nbM, 256, SM_BIG>>>(buf1, w2h, w2l, tmp);
    k_agg128h<<<nbA, TB>>>(tmp, buf1);

    // corr_2 metric on h2
    k_zero_G<<<(HID * HID + TB - 1) / TB, TB>>>();
    k_gram_mma<HID><<<296, 256>>>(buf1);
    k_finalize<HID><<<1, 256>>>(out + NNODES * COUT);

    // layer 3: relu(h2) @ W3 -> agg directly into d_out
    k_tgemm<HID, COUT, true><<<nbM, 256, SM_SML>>>(buf1, w3h, w3l, tmp);
    k_agg64h<<<nbA, TB>>>(tmp, out);

    // corr metric on h3
    k_zero_G<<<(HID * HID + TB - 1) / TB, TB>>>();
    k_gram_mma<COUT><<<296, 256>>>(out);
    k_finalize<COUT><<<1, 256>>>(out + NNODES * COUT + 1);
}